// round 16
// baseline (speedup 1.0000x reference)
#include <cuda_runtime.h>
#include <math.h>
#include <stdint.h>

#define NN 4096
#define DD 2048
#define CC 8192
#define MARGIN_F 0.3f
#define EPSLS 0.1f

#if defined(__CUDA_ARCH__) && (__CUDA_ARCH__ >= 1000) &&                        \
    (defined(__CUDA_ARCH_FEAT_SM103_ALL) || defined(__CUDA_ARCH_FEAT_SM100_ALL) || \
     defined(__CUDA_ARCH_SPECIFIC__) || defined(__CUDA_ARCH_FAMILY_SPECIFIC__))
#define TC_OK 1
#else
#define TC_OK 0
#endif

// ---------------- device scratch ----------------
__device__ float g_xx[NN];
__device__ float g_ce_row[NN];
__device__ int   g_tgt[NN];
__device__ int   g_ctr;   // k_dist completion counter (reset by k_prep)

// ---------------- PTX helpers ----------------
__device__ __forceinline__ uint32_t smem_u32(const void* p) {
    uint32_t a;
    asm("{ .reg .u64 t; cvta.to.shared.u64 t, %1; cvt.u32.u64 %0, t; }"
        : "=r"(a) : "l"(p));
    return a;
}
__device__ __forceinline__ void cp_async16(uint32_t dst, const void* src) {
    asm volatile("cp.async.cg.shared.global [%0], [%1], 16;"
                 :: "r"(dst), "l"(src) : "memory");
}

#if TC_OK
// .noinc is load-bearing: plain arrive is increment-then-arrive (net zero).
__device__ __forceinline__ void cp_mbar_arrive_noinc(uint32_t mbar) {
    asm volatile("cp.async.mbarrier.arrive.noinc.shared::cta.b64 [%0];"
                 :: "r"(mbar) : "memory");
}
__device__ __forceinline__ void mbar_init(uint32_t a, uint32_t n) {
    asm volatile("mbarrier.init.shared.b64 [%0], %1;" :: "r"(a), "r"(n) : "memory");
}
__device__ __forceinline__ void mbar_wait(uint32_t a, uint32_t ph) {
    asm volatile(
        "{\n\t"
        ".reg .pred P;\n\t"
        "WL_%=:\n\t"
        "mbarrier.try_wait.parity.acquire.cta.shared::cta.b64 P, [%0], %1, 0x989680;\n\t"
        "@P bra WD_%=;\n\t"
        "bra WL_%=;\n\t"
        "WD_%=:\n\t"
        "}" :: "r"(a), "r"(ph) : "memory");
}
__device__ __forceinline__ void tmem_alloc(uint32_t smem_dst, uint32_t ncols) {
    asm volatile("tcgen05.alloc.cta_group::1.sync.aligned.shared::cta.b32 [%0], %1;"
                 :: "r"(smem_dst), "r"(ncols) : "memory");
}
__device__ __forceinline__ void tmem_dealloc(uint32_t tmem, uint32_t ncols) {
    asm volatile("tcgen05.dealloc.cta_group::1.sync.aligned.b32 %0, %1;"
                 :: "r"(tmem), "r"(ncols));
}
__device__ __forceinline__ void tmem_relinq() {
    asm volatile("tcgen05.relinquish_alloc_permit.cta_group::1.sync.aligned;");
}
__device__ __forceinline__ void mma_commit(uint32_t mbar) {
    asm volatile("tcgen05.commit.cta_group::1.mbarrier::arrive::one.shared::cluster.b64 [%0];"
                 :: "r"(mbar) : "memory");
}
__device__ __forceinline__ void fence_async_smem() {
    asm volatile("fence.proxy.async.shared::cta;" ::: "memory");
}
__device__ __forceinline__ void tc_fence_after() {
    asm volatile("tcgen05.fence::after_thread_sync;" ::: "memory");
}
__device__ __forceinline__ void tc_fence_before() {
    asm volatile("tcgen05.fence::before_thread_sync;" ::: "memory");
}
__device__ __forceinline__ void tc_wait_ld() {
    asm volatile("tcgen05.wait::ld.sync.aligned;" ::: "memory");
}
__device__ __forceinline__ void mma_tf32_ss(uint32_t d_tmem, uint64_t a_desc,
                                            uint64_t b_desc, uint32_t idesc,
                                            uint32_t en) {
    asm volatile(
        "{\n\t"
        ".reg .pred p;\n\t"
        "setp.ne.u32 p, %5, 0;\n\t"
        "tcgen05.mma.cta_group::1.kind::tf32 [%0], %1, %2, %3, {%4, %4, %4, %4}, p;\n\t"
        "}"
        :: "r"(d_tmem), "l"(a_desc), "l"(b_desc), "r"(idesc), "r"(0u), "r"(en)
        : "memory");
}
#define LDTM_X32(r, addr)                                                        \
    asm volatile(                                                                \
        "tcgen05.ld.sync.aligned.32x32b.x32.b32 "                                \
        "{%0, %1, %2, %3, %4, %5, %6, %7, "                                      \
        " %8, %9, %10, %11, %12, %13, %14, %15, "                                \
        " %16, %17, %18, %19, %20, %21, %22, %23, "                              \
        " %24, %25, %26, %27, %28, %29, %30, %31}, [%32];"                       \
        : "=r"((r)[0]),  "=r"((r)[1]),  "=r"((r)[2]),  "=r"((r)[3]),             \
          "=r"((r)[4]),  "=r"((r)[5]),  "=r"((r)[6]),  "=r"((r)[7]),             \
          "=r"((r)[8]),  "=r"((r)[9]),  "=r"((r)[10]), "=r"((r)[11]),            \
          "=r"((r)[12]), "=r"((r)[13]), "=r"((r)[14]), "=r"((r)[15]),            \
          "=r"((r)[16]), "=r"((r)[17]), "=r"((r)[18]), "=r"((r)[19]),            \
          "=r"((r)[20]), "=r"((r)[21]), "=r"((r)[22]), "=r"((r)[23]),            \
          "=r"((r)[24]), "=r"((r)[25]), "=r"((r)[26]), "=r"((r)[27]),            \
          "=r"((r)[28]), "=r"((r)[29]), "=r"((r)[30]), "=r"((r)[31])             \
        : "r"(addr))

// SW64 K-major smem descriptor: layout=4, version=1, SBO=32, LBO=1
// (64-byte rows; atom = 8 rows x 64B = 512B)
__device__ __forceinline__ uint64_t make_desc64(uint32_t smem_addr) {
    const uint64_t base = (uint64_t(4) << 61) | (uint64_t(1) << 46) |
                          (uint64_t(32) << 32) | (uint64_t(1) << 16);
    return base | ((uint64_t)(smem_addr >> 4) & 0x3FFF);
}
#define MMA_IDESC ((1u << 4) | (2u << 7) | (2u << 10) | (32u << 17) | (8u << 24))
#endif  // TC_OK

// ---------------- fused prep: targets + out-init + ||E_r||^2 + CE row -------
__global__ void __launch_bounds__(512) k_prep(const float* __restrict__ E,
                                              const float* __restrict__ P,
                                              const int* __restrict__ tgt,
                                              float* __restrict__ out) {
    int r = blockIdx.x;
    int t = threadIdx.x;
    int lane = t & 31, wrp = t >> 5;  // 16 warps

    int trg = min(max(tgt[r], 0), CC - 1);
    if (t == 0) {
        g_tgt[r] = trg;
        out[2 + r] = 0.0f;                       // d2_ap max-acc (>=0)
        ((int*)out)[2 + NN + r] = 0x7F800000;    // d2_an min-acc = +inf
        if (r == 0) g_ctr = 0;                   // reset k_dist completion ctr
    }

    const float4* erow = (const float4*)(E + (size_t)r * DD);
    float4 ev = erow[t];
    float sq = ev.x * ev.x + ev.y * ev.y + ev.z * ev.z + ev.w * ev.w;

    const float4* prow = (const float4*)(P + (size_t)r * CC);
    float4 v[4];
    float mx = -INFINITY, s = 0.f;
#pragma unroll
    for (int i = 0; i < 4; i++) {
        v[i] = prow[t + i * 512];
        mx = fmaxf(mx, fmaxf(fmaxf(v[i].x, v[i].y), fmaxf(v[i].z, v[i].w)));
        s += v[i].x + v[i].y + v[i].z + v[i].w;
    }

    __shared__ float smx[16], ssm[16], sse[16], sxx[16];
#pragma unroll
    for (int o = 16; o > 0; o >>= 1) {
        mx = fmaxf(mx, __shfl_xor_sync(0xFFFFFFFF, mx, o));
        s += __shfl_xor_sync(0xFFFFFFFF, s, o);
        sq += __shfl_xor_sync(0xFFFFFFFF, sq, o);
    }
    if (lane == 0) { smx[wrp] = mx; ssm[wrp] = s; sxx[wrp] = sq; }
    __syncthreads();
    if (wrp == 0) {
        float m2 = (lane < 16) ? smx[lane] : -INFINITY;
        float s2 = (lane < 16) ? ssm[lane] : 0.f;
        float q2 = (lane < 16) ? sxx[lane] : 0.f;
#pragma unroll
        for (int o = 8; o > 0; o >>= 1) {
            m2 = fmaxf(m2, __shfl_xor_sync(0xFFFFFFFF, m2, o));
            s2 += __shfl_xor_sync(0xFFFFFFFF, s2, o);
            q2 += __shfl_xor_sync(0xFFFFFFFF, q2, o);
        }
        if (lane == 0) {
            smx[0] = m2; ssm[0] = s2;
            g_xx[r] = q2;
        }
    }
    __syncthreads();
    mx = smx[0];
    s  = ssm[0];

    float se = 0.f;
#pragma unroll
    for (int i = 0; i < 4; i++) {
        se += __expf(v[i].x - mx) + __expf(v[i].y - mx) +
              __expf(v[i].z - mx) + __expf(v[i].w - mx);
    }
#pragma unroll
    for (int o = 16; o > 0; o >>= 1) se += __shfl_xor_sync(0xFFFFFFFF, se, o);
    if (lane == 0) sse[wrp] = se;
    __syncthreads();
    if (t == 0) {
        float tot = 0.f;
#pragma unroll
        for (int i = 0; i < 16; i++) tot += sse[i];
        float lse = mx + logf(tot);
        float lt  = P[(size_t)r * CC + trg];
        g_ce_row[r] = lse - (1.f - EPSLS) * lt - EPSLS * (s / (float)CC);
    }
}

// ---------------- symmetric Gram + batch-hard mining, warp-specialized -------
// 136 upper-tri tiles, 256x256 per CTA. K chunks of 16 (SW64 layout, 64B rows),
// 6-stage ring (32KB/stage) to absorb cp.async completion jitter.
#define NSTAGE 6
#define STG_BASE 16384
#define STG_SZ   32768
#define DSMEM_BYTES (STG_BASE + NSTAGE * STG_SZ + 1024)

__global__ void __maxnreg__(88) k_dist(const float* __restrict__ E,
                                       float* __restrict__ out) {
    extern __shared__ char dsm_raw[];
    char* dsm = (char*)(((uintptr_t)dsm_raw + 1023) & ~(uintptr_t)1023);
    int tid = threadIdx.x;

    int bi = 0, rem = blockIdx.x;
#pragma unroll 1
    while (rem >= 16 - bi) { rem -= 16 - bi; bi++; }
    int bj = bi + rem;
    int row0 = bi * 256, col0 = bj * 256;
    bool offdiag = (bi != bj);

#if TC_OK
    uint32_t sb = smem_u32(dsm);
    // smem map: 0 tmem ptr | 16..16+6*8 full[0..5] | 64..64+6*8 empty[0..5] | 112 done
    float* xR = (float*)(dsm + 128);
    float* xC = (float*)(dsm + 1152);
    int*   tR = (int*)(dsm + 2176);
    int*   tC = (int*)(dsm + 3200);
    int* rowap = (int*)(dsm + 4224);
    int* rowan = (int*)(dsm + 5248);
    int* colap = (int*)(dsm + 6272);
    int* colan = (int*)(dsm + 7296);
    int wid = tid >> 5, lane = tid & 31;

    if (wid == 0) {
        tmem_alloc(sb + 0, 512);
        tmem_relinq();
    }
    if (tid == 0) {
#pragma unroll
        for (int s = 0; s < NSTAGE; s++) {
            mbar_init(sb + 16 + s * 8, 256);  // full
            mbar_init(sb + 64 + s * 8, 1);    // empty
        }
        mbar_init(sb + 112, 1);               // done
    }
    if (tid < 256) {
        xR[tid] = g_xx[row0 + tid];
        tR[tid] = g_tgt[row0 + tid];
        rowap[tid] = 0;
        colap[tid] = 0;
    } else {
        int j = tid - 256;
        xC[j] = g_xx[col0 + j];
        tC[j] = g_tgt[col0 + j];
        rowan[j] = 0x7F800000;
        colan[j] = 0x7F800000;
    }
    __syncthreads();
    uint32_t tmem;
    asm volatile("ld.shared.b32 %0, [%1];" : "=r"(tmem) : "r"(sb + 0));

    const int NC = DD / 16;  // 128 chunks of K=16

    if (wid < 8) {
        // producers: per chunk, 4 A + 4 B float4 per thread (1024 f4/operand)
        uint32_t offs[4];
        int rows[4], qs[4];
#pragma unroll
        for (int i = 0; i < 4; i++) {
            int idx = tid + i * 256;
            int r = idx >> 2, q = idx & 3;
            uint32_t off = (uint32_t)(r * 64 + q * 16);
            off ^= (off >> 3) & 0x30;   // SW64 swizzle
            offs[i] = off;
            rows[i] = r;
            qs[i] = q * 4;
        }
        const float* EA = E + (size_t)row0 * DD;
        const float* EB = E + (size_t)col0 * DD;
        uint32_t eph[NSTAGE] = {0, 0, 0, 0, 0, 0};
#pragma unroll 1
        for (int c = 0; c < NC; c++) {
            int s = c % NSTAGE;
            if (c >= NSTAGE) {
                mbar_wait(sb + 64 + s * 8, eph[s]);
                eph[s] ^= 1;
            }
            uint32_t A_s = sb + STG_BASE + s * STG_SZ;
            uint32_t B_s = A_s + 16384u;
            int k0 = c * 16;
#pragma unroll
            for (int i = 0; i < 4; i++)
                cp_async16(A_s + offs[i], EA + (size_t)rows[i] * DD + k0 + qs[i]);
            if (offdiag) {
#pragma unroll
                for (int i = 0; i < 4; i++)
                    cp_async16(B_s + offs[i], EB + (size_t)rows[i] * DD + k0 + qs[i]);
            }
            cp_mbar_arrive_noinc(sb + 16 + s * 8);
        }
    } else if (wid == 8 && lane == 0) {
        // MMA issuer: 2 k-steps x 2 row-halves per chunk
        uint32_t fph[NSTAGE] = {0, 0, 0, 0, 0, 0};
#pragma unroll 1
        for (int c = 0; c < NC; c++) {
            int s = c % NSTAGE;
            mbar_wait(sb + 16 + s * 8, fph[s]);
            fph[s] ^= 1;
            fence_async_smem();
            uint32_t A_s = sb + STG_BASE + s * STG_SZ;
            uint64_t a0 = make_desc64(A_s);
            uint64_t a1 = make_desc64(A_s + 8192);
            uint64_t bd = offdiag ? make_desc64(A_s + 16384) : a0;
            uint32_t en = (c != 0);
#pragma unroll
            for (int ks = 0; ks < 2; ks++) {
                uint32_t e = en | (ks != 0);
                mma_tf32_ss(tmem,       a0 + ks * 2, bd + ks * 2, MMA_IDESC, e);
                mma_tf32_ss(tmem + 256, a1 + ks * 2, bd + ks * 2, MMA_IDESC, e);
            }
            mma_commit(sb + 64 + s * 8);
        }
        mma_commit(sb + 112);
    }

    __syncthreads();
    mbar_wait(sb + 112, 0);
    tc_fence_after();

    // Epilogue: warp w -> subpartition s_=w&3, col group g_=w>>2 (64 cols)
    int s_ = wid & 3, g_ = wid >> 2;
#pragma unroll
    for (int h = 0; h < 2; h++) {
        int r_tile = h * 128 + s_ * 32 + lane;
        float xr = xR[r_tile];
        int   trg = tR[r_tile];
        float mp = 0.f, mn = INFINITY;
#pragma unroll
        for (int cb = 0; cb < 2; cb++) {
            uint32_t regs[32];
            LDTM_X32(regs, tmem + h * 256 + g_ * 64 + cb * 32);
            tc_wait_ld();
#pragma unroll
            for (int j = 0; j < 32; j++) {
                int cl = g_ * 64 + cb * 32 + j;
                float g  = __uint_as_float(regs[j]);
                float d2 = fmaxf(xr + xC[cl] - 2.f * g, 0.f);
                bool match = (trg == tC[cl]);
                if (match) mp = fmaxf(mp, d2);
                else       mn = fminf(mn, d2);
                if (offdiag) {
                    float cp = match ? d2 : -1.f;
                    float cn = match ? INFINITY : d2;
#pragma unroll
                    for (int o = 16; o > 0; o >>= 1) {
                        cp = fmaxf(cp, __shfl_xor_sync(0xFFFFFFFF, cp, o));
                        cn = fminf(cn, __shfl_xor_sync(0xFFFFFFFF, cn, o));
                    }
                    if (lane == 0) {
                        atomicMax(&colap[cl], __float_as_int(cp));
                        atomicMin(&colan[cl], __float_as_int(cn));
                    }
                }
            }
        }
        atomicMax(&rowap[r_tile], __float_as_int(mp));
        atomicMin(&rowan[r_tile], __float_as_int(mn));
    }
    tc_fence_before();
    __syncthreads();

    if (tid < 256) {
        atomicMax((int*)&out[2 + row0 + tid],      rowap[tid]);
        atomicMin((int*)&out[2 + NN + row0 + tid], rowan[tid]);
        if (offdiag) {
            atomicMax((int*)&out[2 + col0 + tid],      colap[tid]);
            atomicMin((int*)&out[2 + NN + col0 + tid], colan[tid]);
        }
    }
    __syncthreads();
    if (wid == 0) tmem_dealloc(tmem, 512);

#else  // ---------- generic-arch fallback: FFMA SGEMM, two passes if offdiag ---
    float* As = (float*)(dsm);
    float* Bs = (float*)(dsm + 16896);
    float* xR = (float*)(dsm + 33792);
    float* xC = (float*)(dsm + 34816);
    int*   tR = (int*)(dsm + 35840);
    int*   tC = (int*)(dsm + 36864);
#define AS(k, r) As[(k) * 264 + (r)]
#define BS(k, r) Bs[(k) * 264 + (r)]

    int tx = tid & 15, ty = tid >> 4;
    int npass = offdiag ? 2 : 1;
    for (int p = 0; p < npass; p++) {
        int r0 = p ? col0 : row0;
        int c0base = p ? row0 : col0;
        if (tid < 256) {
            xR[tid] = g_xx[r0 + tid];
            tR[tid] = g_tgt[r0 + tid];
        } else {
            int j = tid - 256;
            xC[j] = g_xx[c0base + j];
            tC[j] = g_tgt[c0base + j];
        }
        __syncthreads();
        for (int hh = 0; hh < 2; hh++) {
            int c0 = c0base + hh * 128;
            float acc[8][8];
#pragma unroll
            for (int m = 0; m < 8; m++)
#pragma unroll
                for (int n = 0; n < 8; n++) acc[m][n] = 0.f;
            for (int k0 = 0; k0 < DD; k0 += 16) {
#pragma unroll
                for (int l = 0; l < 2; l++) {
                    int q = tid + l * 512;
                    int r = q >> 2, kq = (q & 3) << 2;
                    float4 v = *(const float4*)(E + (size_t)(r0 + r) * DD + k0 + kq);
                    AS(kq + 0, r) = v.x; AS(kq + 1, r) = v.y;
                    AS(kq + 2, r) = v.z; AS(kq + 3, r) = v.w;
                }
                if (tid < 512) {
                    int q = tid;
                    int r = q >> 2, kq = (q & 3) << 2;
                    float4 w = *(const float4*)(E + (size_t)(c0 + r) * DD + k0 + kq);
                    BS(kq + 0, r) = w.x; BS(kq + 1, r) = w.y;
                    BS(kq + 2, r) = w.z; BS(kq + 3, r) = w.w;
                }
                __syncthreads();
#pragma unroll
                for (int k = 0; k < 16; k++) {
                    float a[8], b[8];
#pragma unroll
                    for (int m = 0; m < 8; m++) a[m] = AS(k, ty + m * 32);
#pragma unroll
                    for (int n = 0; n < 8; n++) b[n] = BS(k, tx + n * 16);
#pragma unroll
                    for (int m = 0; m < 8; m++)
#pragma unroll
                        for (int n = 0; n < 8; n++)
                            acc[m][n] = fmaf(a[m], b[n], acc[m][n]);
                }
                __syncthreads();
            }
#pragma unroll
            for (int m = 0; m < 8; m++) {
                int   lr  = ty + m * 32;
                int   trg = tR[lr];
                float xr  = xR[lr];
                float mp = 0.f, mn = INFINITY;
#pragma unroll
                for (int n = 0; n < 8; n++) {
                    int   lc = hh * 128 + tx + n * 16;
                    float d2 = fmaxf(xr + xC[lc] - 2.f * acc[m][n], 0.f);
                    if (trg == tC[lc]) mp = fmaxf(mp, d2);
                    else               mn = fminf(mn, d2);
                }
#pragma unroll
                for (int o = 8; o > 0; o >>= 1) {
                    mp = fmaxf(mp, __shfl_xor_sync(0xFFFFFFFF, mp, o));
                    mn = fminf(mn, __shfl_xor_sync(0xFFFFFFFF, mn, o));
                }
                if (tx == 0) {
                    atomicMax((int*)&out[2 + r0 + lr],      __float_as_int(mp));
                    atomicMin((int*)&out[2 + NN + r0 + lr], __float_as_int(mn));
                }
            }
            __syncthreads();
        }
        __syncthreads();
    }
#undef AS
#undef BS
#endif

    // ---- last-CTA final reduce ----
    __shared__ int s_last;
    __threadfence();
    if (tid == 0) s_last = (atomicAdd(&g_ctr, 1) == 135);
    __syncthreads();
    if (s_last) {
        __threadfence();
        __shared__ float s1[512], s2[512];
        int nt = blockDim.x;
        float str = 0.f, sce = 0.f;
        for (int i = tid; i < NN; i += nt) {
            float ap = sqrtf(fmaxf(out[2 + i],      1e-12f));
            float an = sqrtf(fmaxf(out[2 + NN + i], 1e-12f));
            out[2 + i]      = ap;
            out[2 + NN + i] = an;
            str += fmaxf(ap - an + MARGIN_F, 0.f);
            sce += g_ce_row[i];
        }
        s1[tid] = str; s2[tid] = sce;
        __syncthreads();
        for (int o = nt >> 1; o > 0; o >>= 1) {
            if (tid < o) { s1[tid] += s1[tid + o]; s2[tid] += s2[tid + o]; }
            __syncthreads();
        }
        if (tid == 0) {
            out[0] = s2[0] / (float)NN;  // id_loss
            out[1] = s1[0] / (float)NN;  // tri_loss
        }
    }
}

extern "C" void kernel_launch(void* const* d_in, const int* in_sizes, int n_in,
                              void* d_out, int out_size) {
    const float* E = (const float*)d_in[0];
    const float* P = (const float*)d_in[1];
    const int*   T = (const int*)d_in[2];
    float* out = (float*)d_out;

    cudaFuncSetAttribute(k_dist, cudaFuncAttributeMaxDynamicSharedMemorySize,
                         DSMEM_BYTES);

    k_prep<<<NN, 512>>>(E, P, T, out);
    k_dist<<<136, 512, DSMEM_BYTES>>>(E, out);
}

// round 17
// speedup vs baseline: 1.1904x; 1.1904x over previous
#include <cuda_runtime.h>
#include <math.h>
#include <stdint.h>

#define NN 4096
#define DD 2048
#define CC 8192
#define MARGIN_F 0.3f
#define EPSLS 0.1f

#if defined(__CUDA_ARCH__) && (__CUDA_ARCH__ >= 1000) &&                        \
    (defined(__CUDA_ARCH_FEAT_SM103_ALL) || defined(__CUDA_ARCH_FEAT_SM100_ALL) || \
     defined(__CUDA_ARCH_SPECIFIC__) || defined(__CUDA_ARCH_FAMILY_SPECIFIC__))
#define TC_OK 1
#else
#define TC_OK 0
#endif

// ---------------- device scratch ----------------
__device__ float g_xx[NN];
__device__ float g_ce_row[NN];
__device__ int   g_tgt[NN];
__device__ int   g_ctr;   // k_dist completion counter (reset by k_prep)

// ---------------- PTX helpers ----------------
__device__ __forceinline__ uint32_t smem_u32(const void* p) {
    uint32_t a;
    asm("{ .reg .u64 t; cvta.to.shared.u64 t, %1; cvt.u32.u64 %0, t; }"
        : "=r"(a) : "l"(p));
    return a;
}
__device__ __forceinline__ void cp_async16(uint32_t dst, const void* src) {
    asm volatile("cp.async.cg.shared.global [%0], [%1], 16;"
                 :: "r"(dst), "l"(src) : "memory");
}
__device__ __forceinline__ float4 ldcs4(const float4* p) {
    float4 v;
    asm volatile("ld.global.cs.v4.f32 {%0, %1, %2, %3}, [%4];"
                 : "=f"(v.x), "=f"(v.y), "=f"(v.z), "=f"(v.w) : "l"(p));
    return v;
}

#if TC_OK
// .noinc is load-bearing: plain arrive is increment-then-arrive (net zero).
__device__ __forceinline__ void cp_mbar_arrive_noinc(uint32_t mbar) {
    asm volatile("cp.async.mbarrier.arrive.noinc.shared::cta.b64 [%0];"
                 :: "r"(mbar) : "memory");
}
__device__ __forceinline__ void mbar_init(uint32_t a, uint32_t n) {
    asm volatile("mbarrier.init.shared.b64 [%0], %1;" :: "r"(a), "r"(n) : "memory");
}
__device__ __forceinline__ void mbar_wait(uint32_t a, uint32_t ph) {
    asm volatile(
        "{\n\t"
        ".reg .pred P;\n\t"
        "WL_%=:\n\t"
        "mbarrier.try_wait.parity.acquire.cta.shared::cta.b64 P, [%0], %1, 0x989680;\n\t"
        "@P bra WD_%=;\n\t"
        "bra WL_%=;\n\t"
        "WD_%=:\n\t"
        "}" :: "r"(a), "r"(ph) : "memory");
}
__device__ __forceinline__ void tmem_alloc(uint32_t smem_dst, uint32_t ncols) {
    asm volatile("tcgen05.alloc.cta_group::1.sync.aligned.shared::cta.b32 [%0], %1;"
                 :: "r"(smem_dst), "r"(ncols) : "memory");
}
__device__ __forceinline__ void tmem_dealloc(uint32_t tmem, uint32_t ncols) {
    asm volatile("tcgen05.dealloc.cta_group::1.sync.aligned.b32 %0, %1;"
                 :: "r"(tmem), "r"(ncols));
}
__device__ __forceinline__ void tmem_relinq() {
    asm volatile("tcgen05.relinquish_alloc_permit.cta_group::1.sync.aligned;");
}
__device__ __forceinline__ void mma_commit(uint32_t mbar) {
    asm volatile("tcgen05.commit.cta_group::1.mbarrier::arrive::one.shared::cluster.b64 [%0];"
                 :: "r"(mbar) : "memory");
}
__device__ __forceinline__ void fence_async_smem() {
    asm volatile("fence.proxy.async.shared::cta;" ::: "memory");
}
__device__ __forceinline__ void tc_fence_after() {
    asm volatile("tcgen05.fence::after_thread_sync;" ::: "memory");
}
__device__ __forceinline__ void tc_fence_before() {
    asm volatile("tcgen05.fence::before_thread_sync;" ::: "memory");
}
__device__ __forceinline__ void tc_wait_ld() {
    asm volatile("tcgen05.wait::ld.sync.aligned;" ::: "memory");
}
__device__ __forceinline__ void mma_tf32_ss(uint32_t d_tmem, uint64_t a_desc,
                                            uint64_t b_desc, uint32_t idesc,
                                            uint32_t en) {
    asm volatile(
        "{\n\t"
        ".reg .pred p;\n\t"
        "setp.ne.u32 p, %5, 0;\n\t"
        "tcgen05.mma.cta_group::1.kind::tf32 [%0], %1, %2, %3, {%4, %4, %4, %4}, p;\n\t"
        "}"
        :: "r"(d_tmem), "l"(a_desc), "l"(b_desc), "r"(idesc), "r"(0u), "r"(en)
        : "memory");
}
#define LDTM_X32(r, addr)                                                        \
    asm volatile(                                                                \
        "tcgen05.ld.sync.aligned.32x32b.x32.b32 "                                \
        "{%0, %1, %2, %3, %4, %5, %6, %7, "                                      \
        " %8, %9, %10, %11, %12, %13, %14, %15, "                                \
        " %16, %17, %18, %19, %20, %21, %22, %23, "                              \
        " %24, %25, %26, %27, %28, %29, %30, %31}, [%32];"                       \
        : "=r"((r)[0]),  "=r"((r)[1]),  "=r"((r)[2]),  "=r"((r)[3]),             \
          "=r"((r)[4]),  "=r"((r)[5]),  "=r"((r)[6]),  "=r"((r)[7]),             \
          "=r"((r)[8]),  "=r"((r)[9]),  "=r"((r)[10]), "=r"((r)[11]),            \
          "=r"((r)[12]), "=r"((r)[13]), "=r"((r)[14]), "=r"((r)[15]),            \
          "=r"((r)[16]), "=r"((r)[17]), "=r"((r)[18]), "=r"((r)[19]),            \
          "=r"((r)[20]), "=r"((r)[21]), "=r"((r)[22]), "=r"((r)[23]),            \
          "=r"((r)[24]), "=r"((r)[25]), "=r"((r)[26]), "=r"((r)[27]),            \
          "=r"((r)[28]), "=r"((r)[29]), "=r"((r)[30]), "=r"((r)[31])             \
        : "r"(addr))

// SW128 K-major smem descriptor
__device__ __forceinline__ uint64_t make_desc(uint32_t smem_addr) {
    const uint64_t base = (uint64_t(2) << 61) | (uint64_t(1) << 46) |
                          (uint64_t(64) << 32) | (uint64_t(1) << 16);
    return base | ((uint64_t)(smem_addr >> 4) & 0x3FFF);
}
#define MMA_IDESC ((1u << 4) | (2u << 7) | (2u << 10) | (32u << 17) | (8u << 24))
#endif  // TC_OK

// ---------------- fused prep: targets + out-init + ||E_r||^2 + CE row -------
__global__ void __launch_bounds__(512) k_prep(const float* __restrict__ E,
                                              const float* __restrict__ P,
                                              const int* __restrict__ tgt,
                                              float* __restrict__ out) {
    int r = blockIdx.x;
    int t = threadIdx.x;
    int lane = t & 31, wrp = t >> 5;  // 16 warps

    int trg = min(max(tgt[r], 0), CC - 1);
    if (t == 0) {
        g_tgt[r] = trg;
        out[2 + r] = 0.0f;                       // d2_ap max-acc (>=0)
        ((int*)out)[2 + NN + r] = 0x7F800000;    // d2_an min-acc = +inf
        if (r == 0) g_ctr = 0;                   // reset k_dist completion ctr
    }

    // ---- xx: 2048 floats = 512 float4, one per thread ----
    const float4* erow = (const float4*)(E + (size_t)r * DD);
    float4 ev = erow[t];
    float sq = ev.x * ev.x + ev.y * ev.y + ev.z * ev.z + ev.w * ev.w;

    // ---- CE pass 1: streaming loads (P is read-once; keep E in L2) ----
    const float4* prow = (const float4*)(P + (size_t)r * CC);
    float4 v[4];
    float mx = -INFINITY, s = 0.f;
#pragma unroll
    for (int i = 0; i < 4; i++) {
        v[i] = ldcs4(prow + t + i * 512);
        mx = fmaxf(mx, fmaxf(fmaxf(v[i].x, v[i].y), fmaxf(v[i].z, v[i].w)));
        s += v[i].x + v[i].y + v[i].z + v[i].w;
    }

    __shared__ float smx[16], ssm[16], sse[16], sxx[16];
#pragma unroll
    for (int o = 16; o > 0; o >>= 1) {
        mx = fmaxf(mx, __shfl_xor_sync(0xFFFFFFFF, mx, o));
        s += __shfl_xor_sync(0xFFFFFFFF, s, o);
        sq += __shfl_xor_sync(0xFFFFFFFF, sq, o);
    }
    if (lane == 0) { smx[wrp] = mx; ssm[wrp] = s; sxx[wrp] = sq; }
    __syncthreads();
    if (wrp == 0) {
        float m2 = (lane < 16) ? smx[lane] : -INFINITY;
        float s2 = (lane < 16) ? ssm[lane] : 0.f;
        float q2 = (lane < 16) ? sxx[lane] : 0.f;
#pragma unroll
        for (int o = 8; o > 0; o >>= 1) {
            m2 = fmaxf(m2, __shfl_xor_sync(0xFFFFFFFF, m2, o));
            s2 += __shfl_xor_sync(0xFFFFFFFF, s2, o);
            q2 += __shfl_xor_sync(0xFFFFFFFF, q2, o);
        }
        if (lane == 0) {
            smx[0] = m2; ssm[0] = s2;
            g_xx[r] = q2;
        }
    }
    __syncthreads();
    mx = smx[0];
    s  = ssm[0];

    // ---- CE pass 2: register-resident exp ----
    float se = 0.f;
#pragma unroll
    for (int i = 0; i < 4; i++) {
        se += __expf(v[i].x - mx) + __expf(v[i].y - mx) +
              __expf(v[i].z - mx) + __expf(v[i].w - mx);
    }
#pragma unroll
    for (int o = 16; o > 0; o >>= 1) se += __shfl_xor_sync(0xFFFFFFFF, se, o);
    if (lane == 0) sse[wrp] = se;
    __syncthreads();
    if (t == 0) {
        float tot = 0.f;
#pragma unroll
        for (int i = 0; i < 16; i++) tot += sse[i];
        float lse = mx + logf(tot);
        float lt  = P[(size_t)r * CC + trg];
        g_ce_row[r] = lse - (1.f - EPSLS) * lt - EPSLS * (s / (float)CC);
    }
}

// ---------------- symmetric Gram + batch-hard mining, warp-specialized -------
// 136 upper-tri tiles, 256x256 per CTA, K chunks of 32, 3-stage ring (R15
// config — K=16/6-stage regressed: per-chunk fixed costs dominate, transfer
// is at the LTS cap). Last CTA performs the final reduce.
#define NSTAGE 3
#define STG_BASE 16384
#define STG_SZ   65536
#define DSMEM_BYTES (STG_BASE + NSTAGE * STG_SZ + 1024)

__global__ void __maxnreg__(88) k_dist(const float* __restrict__ E,
                                       float* __restrict__ out) {
    extern __shared__ char dsm_raw[];
    char* dsm = (char*)(((uintptr_t)dsm_raw + 1023) & ~(uintptr_t)1023);
    int tid = threadIdx.x;

    int bi = 0, rem = blockIdx.x;
#pragma unroll 1
    while (rem >= 16 - bi) { rem -= 16 - bi; bi++; }
    int bj = bi + rem;
    int row0 = bi * 256, col0 = bj * 256;
    bool offdiag = (bi != bj);

#if TC_OK
    uint32_t sb = smem_u32(dsm);
    float* xR = (float*)(dsm + 128);
    float* xC = (float*)(dsm + 1152);
    int*   tR = (int*)(dsm + 2176);
    int*   tC = (int*)(dsm + 3200);
    int* rowap = (int*)(dsm + 4224);
    int* rowan = (int*)(dsm + 5248);
    int* colap = (int*)(dsm + 6272);
    int* colan = (int*)(dsm + 7296);
    int wid = tid >> 5, lane = tid & 31;

    if (wid == 0) {
        tmem_alloc(sb + 0, 512);
        tmem_relinq();
    }
    if (tid == 0) {
#pragma unroll
        for (int s = 0; s < NSTAGE; s++) {
            mbar_init(sb + 16 + s * 8, 256);
            mbar_init(sb + 40 + s * 8, 1);
        }
        mbar_init(sb + 64, 1);
    }
    if (tid < 256) {
        xR[tid] = g_xx[row0 + tid];
        tR[tid] = g_tgt[row0 + tid];
        rowap[tid] = 0;
        colap[tid] = 0;
    } else {
        int j = tid - 256;
        xC[j] = g_xx[col0 + j];
        tC[j] = g_tgt[col0 + j];
        rowan[j] = 0x7F800000;
        colan[j] = 0x7F800000;
    }
    __syncthreads();
    uint32_t tmem;
    asm volatile("ld.shared.b32 %0, [%1];" : "=r"(tmem) : "r"(sb + 0));

    const int NC = DD / 32;  // 64 chunks

    if (wid < 8) {
        // producers
        uint32_t offs[8];
        int rows[8], qs[8];
#pragma unroll
        for (int i = 0; i < 8; i++) {
            int idx = tid + i * 256;
            int r = idx >> 3, q = idx & 7;
            uint32_t off = (uint32_t)(r * 128 + q * 16);
            off ^= (off >> 3) & 0x70;
            offs[i] = off;
            rows[i] = r;
            qs[i] = q * 4;
        }
        const float* EA = E + (size_t)row0 * DD;
        const float* EB = E + (size_t)col0 * DD;
        uint32_t eph[NSTAGE] = {0, 0, 0};
#pragma unroll 1
        for (int c = 0; c < NC; c++) {
            int s = c % NSTAGE;
            if (c >= NSTAGE) {
                mbar_wait(sb + 40 + s * 8, eph[s]);
                eph[s] ^= 1;
            }
            uint32_t A_s = sb + STG_BASE + s * STG_SZ;
            uint32_t B_s = A_s + 32768u;
            int k0 = c * 32;
#pragma unroll
            for (int i = 0; i < 8; i++)
                cp_async16(A_s + offs[i], EA + (size_t)rows[i] * DD + k0 + qs[i]);
            if (offdiag) {
#pragma unroll
                for (int i = 0; i < 8; i++)
                    cp_async16(B_s + offs[i], EB + (size_t)rows[i] * DD + k0 + qs[i]);
            }
            cp_mbar_arrive_noinc(sb + 16 + s * 8);
        }
    } else if (wid == 8 && lane == 0) {
        // MMA issuer
        uint32_t fph[NSTAGE] = {0, 0, 0};
#pragma unroll 1
        for (int c = 0; c < NC; c++) {
            int s = c % NSTAGE;
            mbar_wait(sb + 16 + s * 8, fph[s]);
            fph[s] ^= 1;
            fence_async_smem();
            uint32_t A_s = sb + STG_BASE + s * STG_SZ;
            uint64_t a0 = make_desc(A_s);
            uint64_t a1 = make_desc(A_s + 16384);
            uint64_t bd = offdiag ? make_desc(A_s + 32768) : a0;
            uint32_t en = (c != 0);
#pragma unroll
            for (int ks = 0; ks < 4; ks++) {
                uint32_t e = en | (ks != 0);
                mma_tf32_ss(tmem,       a0 + ks * 2, bd + ks * 2, MMA_IDESC, e);
                mma_tf32_ss(tmem + 256, a1 + ks * 2, bd + ks * 2, MMA_IDESC, e);
            }
            mma_commit(sb + 40 + s * 8);
        }
        mma_commit(sb + 64);
    }

    __syncthreads();
    mbar_wait(sb + 64, 0);
    tc_fence_after();

    // Epilogue: warp w -> subpartition s_=w&3, col group g_=w>>2 (64 cols)
    int s_ = wid & 3, g_ = wid >> 2;
#pragma unroll
    for (int h = 0; h < 2; h++) {
        int r_tile = h * 128 + s_ * 32 + lane;
        float xr = xR[r_tile];
        int   trg = tR[r_tile];
        float mp = 0.f, mn = INFINITY;
#pragma unroll
        for (int cb = 0; cb < 2; cb++) {
            uint32_t regs[32];
            LDTM_X32(regs, tmem + h * 256 + g_ * 64 + cb * 32);
            tc_wait_ld();
#pragma unroll
            for (int j = 0; j < 32; j++) {
                int cl = g_ * 64 + cb * 32 + j;
                float g  = __uint_as_float(regs[j]);
                float d2 = fmaxf(xr + xC[cl] - 2.f * g, 0.f);
                bool match = (trg == tC[cl]);
                if (match) mp = fmaxf(mp, d2);
                else       mn = fminf(mn, d2);
                if (offdiag) {
                    float cp = match ? d2 : -1.f;
                    float cn = match ? INFINITY : d2;
#pragma unroll
                    for (int o = 16; o > 0; o >>= 1) {
                        cp = fmaxf(cp, __shfl_xor_sync(0xFFFFFFFF, cp, o));
                        cn = fminf(cn, __shfl_xor_sync(0xFFFFFFFF, cn, o));
                    }
                    if (lane == 0) {
                        atomicMax(&colap[cl], __float_as_int(cp));
                        atomicMin(&colan[cl], __float_as_int(cn));
                    }
                }
            }
        }
        atomicMax(&rowap[r_tile], __float_as_int(mp));
        atomicMin(&rowan[r_tile], __float_as_int(mn));
    }
    tc_fence_before();
    __syncthreads();

    if (tid < 256) {
        atomicMax((int*)&out[2 + row0 + tid],      rowap[tid]);
        atomicMin((int*)&out[2 + NN + row0 + tid], rowan[tid]);
        if (offdiag) {
            atomicMax((int*)&out[2 + col0 + tid],      colap[tid]);
            atomicMin((int*)&out[2 + NN + col0 + tid], colan[tid]);
        }
    }
    __syncthreads();
    if (wid == 0) tmem_dealloc(tmem, 512);

#else  // ---------- generic-arch fallback: FFMA SGEMM, two passes if offdiag ---
    float* As = (float*)(dsm);
    float* Bs = (float*)(dsm + 16896);
    float* xR = (float*)(dsm + 33792);
    float* xC = (float*)(dsm + 34816);
    int*   tR = (int*)(dsm + 35840);
    int*   tC = (int*)(dsm + 36864);
#define AS(k, r) As[(k) * 264 + (r)]
#define BS(k, r) Bs[(k) * 264 + (r)]

    int tx = tid & 15, ty = tid >> 4;
    int npass = offdiag ? 2 : 1;
    for (int p = 0; p < npass; p++) {
        int r0 = p ? col0 : row0;
        int c0base = p ? row0 : col0;
        if (tid < 256) {
            xR[tid] = g_xx[r0 + tid];
            tR[tid] = g_tgt[r0 + tid];
        } else {
            int j = tid - 256;
            xC[j] = g_xx[c0base + j];
            tC[j] = g_tgt[c0base + j];
        }
        __syncthreads();
        for (int hh = 0; hh < 2; hh++) {
            int c0 = c0base + hh * 128;
            float acc[8][8];
#pragma unroll
            for (int m = 0; m < 8; m++)
#pragma unroll
                for (int n = 0; n < 8; n++) acc[m][n] = 0.f;
            for (int k0 = 0; k0 < DD; k0 += 16) {
#pragma unroll
                for (int l = 0; l < 2; l++) {
                    int q = tid + l * 512;
                    int r = q >> 2, kq = (q & 3) << 2;
                    float4 v = *(const float4*)(E + (size_t)(r0 + r) * DD + k0 + kq);
                    AS(kq + 0, r) = v.x; AS(kq + 1, r) = v.y;
                    AS(kq + 2, r) = v.z; AS(kq + 3, r) = v.w;
                }
                if (tid < 512) {
                    int q = tid;
                    int r = q >> 2, kq = (q & 3) << 2;
                    float4 w = *(const float4*)(E + (size_t)(c0 + r) * DD + k0 + kq);
                    BS(kq + 0, r) = w.x; BS(kq + 1, r) = w.y;
                    BS(kq + 2, r) = w.z; BS(kq + 3, r) = w.w;
                }
                __syncthreads();
#pragma unroll
                for (int k = 0; k < 16; k++) {
                    float a[8], b[8];
#pragma unroll
                    for (int m = 0; m < 8; m++) a[m] = AS(k, ty + m * 32);
#pragma unroll
                    for (int n = 0; n < 8; n++) b[n] = BS(k, tx + n * 16);
#pragma unroll
                    for (int m = 0; m < 8; m++)
#pragma unroll
                        for (int n = 0; n < 8; n++)
                            acc[m][n] = fmaf(a[m], b[n], acc[m][n]);
                }
                __syncthreads();
            }
#pragma unroll
            for (int m = 0; m < 8; m++) {
                int   lr  = ty + m * 32;
                int   trg = tR[lr];
                float xr  = xR[lr];
                float mp = 0.f, mn = INFINITY;
#pragma unroll
                for (int n = 0; n < 8; n++) {
                    int   lc = hh * 128 + tx + n * 16;
                    float d2 = fmaxf(xr + xC[lc] - 2.f * acc[m][n], 0.f);
                    if (trg == tC[lc]) mp = fmaxf(mp, d2);
                    else               mn = fminf(mn, d2);
                }
#pragma unroll
                for (int o = 8; o > 0; o >>= 1) {
                    mp = fmaxf(mp, __shfl_xor_sync(0xFFFFFFFF, mp, o));
                    mn = fminf(mn, __shfl_xor_sync(0xFFFFFFFF, mn, o));
                }
                if (tx == 0) {
                    atomicMax((int*)&out[2 + r0 + lr],      __float_as_int(mp));
                    atomicMin((int*)&out[2 + NN + r0 + lr], __float_as_int(mn));
                }
            }
            __syncthreads();
        }
        __syncthreads();
    }
#undef AS
#undef BS
#endif

    // ---- last-CTA final reduce ----
    __shared__ int s_last;
    __threadfence();
    if (tid == 0) s_last = (atomicAdd(&g_ctr, 1) == 135);
    __syncthreads();
    if (s_last) {
        __threadfence();
        __shared__ float s1[512], s2[512];
        int nt = blockDim.x;
        float str = 0.f, sce = 0.f;
        for (int i = tid; i < NN; i += nt) {
            float ap = sqrtf(fmaxf(out[2 + i],      1e-12f));
            float an = sqrtf(fmaxf(out[2 + NN + i], 1e-12f));
            out[2 + i]      = ap;
            out[2 + NN + i] = an;
            str += fmaxf(ap - an + MARGIN_F, 0.f);
            sce += g_ce_row[i];
        }
        s1[tid] = str; s2[tid] = sce;
        __syncthreads();
        for (int o = nt >> 1; o > 0; o >>= 1) {
            if (tid < o) { s1[tid] += s1[tid + o]; s2[tid] += s2[tid + o]; }
            __syncthreads();
        }
        if (tid == 0) {
            out[0] = s2[0] / (float)NN;  // id_loss
            out[1] = s1[0] / (float)NN;  // tri_loss
        }
    }
}

extern "C" void kernel_launch(void* const* d_in, const int* in_sizes, int n_in,
                              void* d_out, int out_size) {
    const float* E = (const float*)d_in[0];
    const float* P = (const float*)d_in[1];
    const int*   T = (const int*)d_in[2];
    float* out = (float*)d_out;

    cudaFuncSetAttribute(k_dist, cudaFuncAttributeMaxDynamicSharedMemorySize,
                         DSMEM_BYTES);

    k_prep<<<NN, 512>>>(E, P, T, out);
    k_dist<<<136, 512, DSMEM_BYTES>>>(E, out);
}